// round 3
// baseline (speedup 1.0000x reference)
#include <cuda_runtime.h>

#define BB 16
#define TT 128
#define DD 1024
#define EE 128
#define HHN 128
#define GG 384           // 3*H
#define NSEQ (BB*TT)     // 2048
#define NGRP (NSEQ/4)    // 512
#define SWS 385          // padded row stride for Whh^T in SMEM

// ---------------- scratch (device globals; no allocation) ----------------
__device__ float g_emb [NSEQ*EE];   // emb[b*T+t][e]
__device__ float g_wemb[NSEQ*EE];   // Wo[e]*emb
__device__ float g_GXa [NSEQ*GG];   // Wih_a@emb + bih_a
__device__ float g_GXb [NSEQ*GG];
__device__ float g_pa  [NSEQ*TT];   // pre_alpha[b*T+i][k]
__device__ float g_sv  [NSEQ*TT];   // s[b*T+i][k] = dot(wemb_j, beta_k)

// ---------------- Kernel 1: emb = x @ W_emb^T ; wemb = Wo .* emb ----------------
// M=2048, N=128, K=1024. grid (32,4), tile 64x32, 256 threads, micro 4x2.
__global__ __launch_bounds__(256) void emb_kernel(
    const float* __restrict__ x, const float* __restrict__ Wemb,
    const float* __restrict__ Wo)
{
    __shared__ float sx[16][68];
    __shared__ float sw[16][36];
    int tid = threadIdx.x;
    int m0 = blockIdx.x * 64;
    int n0 = blockIdx.y * 32;
    int tx = tid & 15, ty = tid >> 4;
    int tm0 = tx * 4, tn0 = ty * 2;

    float acc[4][2];
#pragma unroll
    for (int q = 0; q < 4; q++) { acc[q][0] = 0.f; acc[q][1] = 0.f; }

    for (int kt = 0; kt < DD; kt += 16) {
        {   // x tile 64x16, 4 elems/thread (float4)
            int e = tid * 4; int m = e >> 4; int k = e & 15;
            float4 v = *(const float4*)(x + (size_t)(m0 + m) * DD + kt + k);
            sx[k][m] = v.x; sx[k+1][m] = v.y; sx[k+2][m] = v.z; sx[k+3][m] = v.w;
        }
        {   // W tile 32x16, 2 elems/thread (float2)
            int e = tid * 2; int n = e >> 4; int k = e & 15;
            float2 v = *(const float2*)(Wemb + (size_t)(n0 + n) * DD + kt + k);
            sw[k][n] = v.x; sw[k+1][n] = v.y;
        }
        __syncthreads();
#pragma unroll
        for (int k = 0; k < 16; k++) {
            float a0 = sx[k][tm0], a1 = sx[k][tm0+1], a2 = sx[k][tm0+2], a3 = sx[k][tm0+3];
            float b0 = sw[k][tn0], b1 = sw[k][tn0+1];
            acc[0][0] += a0*b0; acc[0][1] += a0*b1;
            acc[1][0] += a1*b0; acc[1][1] += a1*b1;
            acc[2][0] += a2*b0; acc[2][1] += a2*b1;
            acc[3][0] += a3*b0; acc[3][1] += a3*b1;
        }
        __syncthreads();
    }
#pragma unroll
    for (int q = 0; q < 4; q++)
#pragma unroll
        for (int r = 0; r < 2; r++) {
            int m = m0 + tm0 + q, n = n0 + tn0 + r;
            float v = acc[q][r];
            g_emb [m*EE + n] = v;
            g_wemb[m*EE + n] = v * Wo[n];
        }
}

// ---------------- Kernel 2: GX = emb @ Wih^T + bih (both GRUs) ----------------
// M=2048, N=768 (a:0..383, b:384..767), K=128. grid (32,12), tile 64x64, micro 4x4.
__global__ __launch_bounds__(256) void gx_kernel(
    const float* __restrict__ Wih_a, const float* __restrict__ Wih_b,
    const float* __restrict__ bih_a, const float* __restrict__ bih_b)
{
    __shared__ float se [16][68];
    __shared__ float sw2[16][68];
    int tid = threadIdx.x;
    int m0 = blockIdx.x * 64;
    int n0 = blockIdx.y * 64;
    int tx = tid & 15, ty = tid >> 4;
    int tm0 = tx * 4, tn0 = ty * 4;

    const float* W; const float* bi; float* out; int nb;
    if (n0 < GG) { W = Wih_a; bi = bih_a; out = g_GXa; nb = n0; }
    else         { W = Wih_b; bi = bih_b; out = g_GXb; nb = n0 - GG; }

    float acc[4][4];
#pragma unroll
    for (int q = 0; q < 4; q++)
#pragma unroll
        for (int r = 0; r < 4; r++) acc[q][r] = 0.f;

    for (int kt = 0; kt < EE; kt += 16) {
        {
            int e = tid * 4; int m = e >> 4; int k = e & 15;
            float4 v = *(const float4*)(g_emb + (size_t)(m0 + m) * EE + kt + k);
            se[k][m] = v.x; se[k+1][m] = v.y; se[k+2][m] = v.z; se[k+3][m] = v.w;
        }
        {
            int e = tid * 4; int n = e >> 4; int k = e & 15;
            float4 v = *(const float4*)(W + (size_t)(nb + n) * EE + kt + k);
            sw2[k][n] = v.x; sw2[k+1][n] = v.y; sw2[k+2][n] = v.z; sw2[k+3][n] = v.w;
        }
        __syncthreads();
#pragma unroll
        for (int k = 0; k < 16; k++) {
            float a[4], b[4];
#pragma unroll
            for (int q = 0; q < 4; q++) a[q] = se[k][tm0+q];
#pragma unroll
            for (int r = 0; r < 4; r++) b[r] = sw2[k][tn0+r];
#pragma unroll
            for (int q = 0; q < 4; q++)
#pragma unroll
                for (int r = 0; r < 4; r++) acc[q][r] += a[q]*b[r];
        }
        __syncthreads();
    }
#pragma unroll
    for (int q = 0; q < 4; q++)
#pragma unroll
        for (int r = 0; r < 4; r++) {
            int m = m0 + tm0 + q, n = nb + tn0 + r;
            out[(size_t)m*GG + n] = acc[q][r] + bi[n];
        }
}

// ---------------- Kernel 3: persistent GRU scan (role-split A/B) ----------------
// 384 threads, 1 CTA/SM. Groups of 4 equal-length sequences, snake-ordered queue.
__global__ __launch_bounds__(384, 1) void scan_kernel(
    const float* __restrict__ Whh_a, const float* __restrict__ Whh_b,
    const float* __restrict__ bhh_a, const float* __restrict__ bhh_b,
    const float* __restrict__ Wa,    const float* __restrict__ ba,
    const float* __restrict__ Wb,    const float* __restrict__ bb,
    int RA, int Rtot)
{
    extern __shared__ float smem[];
    float* sW   = smem;                 // 128*385
    float* sB   = sW   + 128*SWS;       // 384: bhh
    float* sV   = sB   + 384;           // 128: A: 0.5*Wa ; B: bb
    float* sh   = sV   + 128;           // 4*132: hidden states (pad to 132)
    float* Ab   = sh   + 4*132;         // 4*384: gate pre-activations (h-part for n)
    float* sIn  = Ab   + 4*384;         // 4*128: gi for n-gate
    float* part = sIn  + 4*128;         // 4*384: Wb partial sums (B)
    float* sred = part + 4*384;         // 4*128: beta*wemb contribs (B)

    int tid = threadIdx.x;
    int lane = tid & 31, warp = tid >> 5;
    bool roleA = (blockIdx.x < RA);
    int rc = roleA ? blockIdx.x : blockIdx.x - RA;
    int R  = roleA ? RA : (Rtot - RA);

    const float* Whh = roleA ? Whh_a : Whh_b;
    const float* bhh = roleA ? bhh_a : bhh_b;
    const float* GX  = roleA ? g_GXa : g_GXb;

    // load Whh^T into SMEM (coalesced global read, conflict-free SMEM write)
    for (int idx = tid; idx < GG*HHN; idx += 384) {
        int g = idx >> 7, h = idx & 127;
        sW[h*SWS + g] = Whh[idx];
    }
    sB[tid] = bhh[tid];
    if (tid < 128) sV[tid] = roleA ? (0.5f * Wa[tid]) : bb[tid];
    float rba = roleA ? ba[0] : 0.f;

    // B: Wb rows in registers (3 threads per output e, 43 h each; scaled by 0.5)
    float wreg[43];
    int e3 = tid / 3, p3 = tid - e3*3, h0 = p3*43;
    if (!roleA) {
#pragma unroll
        for (int q = 0; q < 43; q++) {
            int hh = h0 + q;
            wreg[q] = (hh < HHN) ? 0.5f * Wb[e3*HHN + hh] : 0.f;
        }
    }
    __syncthreads();

    for (int mIdx = 0;; mIdx++) {
        int gsel = mIdx*R + ((mIdx & 1) ? (R - 1 - rc) : rc);   // snake for balance
        if (gsel >= NGRP) break;

        int iS[4], bS[4];
#pragma unroll
        for (int s = 0; s < 4; s++) {
            int n = gsel*4 + s;
            iS[s] = 127 - (n >> 4);    // longest-first ordering
            bS[s] = n & 15;
        }
        int kmax = iS[0];

        __syncthreads();               // protect sh vs previous group's readers
        for (int idx = tid; idx < 4*132; idx += 384) sh[idx] = 0.f;
        __syncthreads();

        for (int k = 0; k <= kmax; k++) {
            bool act[4]; int jS[4]; float gi[4];
#pragma unroll
            for (int s = 0; s < 4; s++) {
                act[s] = (k <= iS[s]);
                jS[s] = act[s] ? (iS[s] - k) : 0;
            }
            // prefetch input-side gates (L2-resident)
#pragma unroll
            for (int s = 0; s < 4; s++)
                gi[s] = GX[(size_t)(bS[s]*TT + jS[s])*GG + tid];

            // prefetch wemb for P4 (B role)
            float wem0 = 0.f, wem1 = 0.f;
            if (!roleA) {
                { int s = tid >> 7, e = tid & 127;
                  wem0 = g_wemb[(bS[s]*TT + jS[s])*EE + e]; }
                if (tid < 128)
                  wem1 = g_wemb[(bS[3]*TT + jS[3])*EE + tid];
            }

            // ---- P1: gh[g] = Whh[g,:]·h  for 4 seqs ----
            float a0 = 0.f, a1 = 0.f, a2 = 0.f, a3 = 0.f;
#pragma unroll 16
            for (int h = 0; h < 128; h++) {
                float w = sW[h*SWS + tid];
                a0 += w * sh[      h];
                a1 += w * sh[132 + h];
                a2 += w * sh[264 + h];
                a3 += w * sh[396 + h];
            }
            {
                float bt = sB[tid];
                if (tid < 256) {   // r,z gates: full pre-activation
                    Ab[       tid] = a0 + gi[0] + bt;
                    Ab[ 384 + tid] = a1 + gi[1] + bt;
                    Ab[ 768 + tid] = a2 + gi[2] + bt;
                    Ab[1152 + tid] = a3 + gi[3] + bt;
                } else {           // n gate: keep h-part and i-part separate
                    int hp = tid - 256;
                    Ab[       tid] = a0 + bt;
                    Ab[ 384 + tid] = a1 + bt;
                    Ab[ 768 + tid] = a2 + bt;
                    Ab[1152 + tid] = a3 + bt;
                    sIn[      hp] = gi[0];
                    sIn[128 + hp] = gi[1];
                    sIn[256 + hp] = gi[2];
                    sIn[384 + hp] = gi[3];
                }
            }
            __syncthreads();

            // ---- P2: GRU state update (512 units) ----
            {
                int s = tid >> 7, hp = tid & 127;
                float ar = Ab[s*384 + hp];
                float az = Ab[s*384 + 128 + hp];
                float hn = Ab[s*384 + 256 + hp];
                float xi = sIn[s*128 + hp];
                float r = __fdividef(1.f, 1.f + __expf(-ar));
                float z = __fdividef(1.f, 1.f + __expf(-az));
                float nn = tanhf(xi + r*hn);
                float ho = sh[s*132 + hp];
                sh[s*132 + hp] = (1.f - z)*nn + z*ho;
            }
            if (tid < 128) {
                int s = 3, hp = tid;
                float ar = Ab[s*384 + hp];
                float az = Ab[s*384 + 128 + hp];
                float hn = Ab[s*384 + 256 + hp];
                float xi = sIn[s*128 + hp];
                float r = __fdividef(1.f, 1.f + __expf(-ar));
                float z = __fdividef(1.f, 1.f + __expf(-az));
                float nn = tanhf(xi + r*hn);
                float ho = sh[s*132 + hp];
                sh[s*132 + hp] = (1.f - z)*nn + z*ho;
            }
            __syncthreads();

            if (roleA) {
                // ---- P3A: pre_alpha = 0.5*Wa·h + ba (warp s -> seq s) ----
                if (warp < 4) {
                    int s = warp;
                    const float* hs = sh + s*132;
                    float p = sV[lane]      * hs[lane]
                            + sV[32 + lane] * hs[32 + lane]
                            + sV[64 + lane] * hs[64 + lane]
                            + sV[96 + lane] * hs[96 + lane];
#pragma unroll
                    for (int o = 16; o > 0; o >>= 1)
                        p += __shfl_xor_sync(0xffffffffu, p, o);
                    if (lane == 0 && act[s])
                        g_pa[(size_t)(bS[s]*TT + iS[s])*TT + k] = p + rba;
                }
            } else {
                // ---- P3B: Wb·(0.5h) partials (registers) ----
#pragma unroll
                for (int s = 0; s < 4; s++) {
                    const float* hs = sh + s*132 + h0;
                    float pp = 0.f;
#pragma unroll
                    for (int q = 0; q < 43; q++) pp += wreg[q] * hs[q];
                    part[s*384 + tid] = pp;
                }
                __syncthreads();
                // ---- P4: beta = tanh(.+bb); contrib = beta*wemb ----
                {
                    int s = tid >> 7, e = tid & 127;
                    float m3 = part[s*384 + e*3] + part[s*384 + e*3 + 1]
                             + part[s*384 + e*3 + 2] + sV[e];
                    sred[tid] = tanhf(m3) * wem0;
                }
                if (tid < 128) {
                    int s = 3, e = tid;
                    float m3 = part[s*384 + e*3] + part[s*384 + e*3 + 1]
                             + part[s*384 + e*3 + 2] + sV[e];
                    sred[384 + tid] = tanhf(m3) * wem1;
                }
                __syncthreads();
                // ---- P5: s[k] = sum_e contrib ----
                if (warp < 4) {
                    int s = warp;
                    float v = sred[s*128 + lane]      + sred[s*128 + 32 + lane]
                            + sred[s*128 + 64 + lane] + sred[s*128 + 96 + lane];
#pragma unroll
                    for (int o = 16; o > 0; o >>= 1)
                        v += __shfl_xor_sync(0xffffffffu, v, o);
                    if (lane == 0 && act[s])
                        g_sv[(size_t)(bS[s]*TT + iS[s])*TT + k] = v;
                }
            }
        } // k
    } // groups
}

// ---------------- Kernel 4: masked softmax combine ----------------
__global__ __launch_bounds__(256) void combine_kernel(
    const float* __restrict__ bo, float* __restrict__ out)
{
    int w = blockIdx.x * 8 + (threadIdx.x >> 5);   // (b,i) flat
    int lane = threadIdx.x & 31;
    if (w >= NSEQ) return;
    int i = w & 127;
    float num = 0.f, den = 0.f;
    for (int k = lane; k <= i; k += 32) {
        float ev = __expf(g_pa[(size_t)w*TT + k]);
        num += ev * g_sv[(size_t)w*TT + k];
        den += ev;
    }
#pragma unroll
    for (int o = 16; o > 0; o >>= 1) {
        num += __shfl_xor_sync(0xffffffffu, num, o);
        den += __shfl_xor_sync(0xffffffffu, den, o);
    }
    if (lane == 0) out[w] = num / den + bo[0];
}

// ---------------- launch ----------------
extern "C" void kernel_launch(void* const* d_in, const int* in_sizes, int n_in,
                              void* d_out, int out_size)
{
    const float* x     = (const float*)d_in[0];
    const float* Wemb  = (const float*)d_in[1];
    const float* Wih_a = (const float*)d_in[2];
    const float* Whh_a = (const float*)d_in[3];
    const float* bih_a = (const float*)d_in[4];
    const float* bhh_a = (const float*)d_in[5];
    const float* Wa    = (const float*)d_in[6];
    const float* ba    = (const float*)d_in[7];
    const float* Wih_b = (const float*)d_in[8];
    const float* Whh_b = (const float*)d_in[9];
    const float* bih_b = (const float*)d_in[10];
    const float* bhh_b = (const float*)d_in[11];
    const float* Wb    = (const float*)d_in[12];
    const float* bb    = (const float*)d_in[13];
    const float* Wo    = (const float*)d_in[14];
    const float* bo    = (const float*)d_in[15];
    float* out = (float*)d_out;

    int dev = 0;
    cudaGetDevice(&dev);
    int sms = 148;
    cudaDeviceGetAttribute(&sms, cudaDevAttrMultiProcessorCount, dev);
    int RA = (int)(sms * 0.427f + 0.5f);
    if (RA < 1) RA = 1;
    if (RA > sms - 1) RA = sms - 1;

    size_t smem_bytes = (size_t)(128*SWS + 384 + 128 + 4*132 + 4*384 + 4*128
                                 + 4*384 + 4*128) * sizeof(float);
    cudaFuncSetAttribute(scan_kernel,
                         cudaFuncAttributeMaxDynamicSharedMemorySize,
                         (int)smem_bytes);

    emb_kernel<<<dim3(32, 4), 256>>>(x, Wemb, Wo);
    gx_kernel<<<dim3(32, 12), 256>>>(Wih_a, Wih_b, bih_a, bih_b);
    scan_kernel<<<sms, 384, smem_bytes>>>(Whh_a, Whh_b, bhh_a, bhh_b,
                                          Wa, ba, Wb, bb, RA, sms);
    combine_kernel<<<NSEQ/8, 256>>>(bo, out);
}